// round 13
// baseline (speedup 1.0000x reference)
#include <cuda_runtime.h>
#include <cstdint>
#include <math.h>

#define S_LEN 128
#define B_SZ  128
#define E_DIM 64
#define H_DIM 8
#define V_SZ  30000
#define T_OUT 12
#define NSAMP (S_LEN * B_SZ)
#define FULLM 0xffffffffu
#define CH    32
#define NCH   (S_LEN / CH)
#define LSTM_WID 7          // highest wid -> arbiter priority
#define NEMB  7             // embed warps 0..6

// ---------------- device scratch ----------------
__device__ float g_h[NSAMP * H_DIM];   // row n = b*S_LEN + s

// ======================================================================
// Compile-time numpy legacy RandomState(1234) replica -> fixed gate list
// ======================================================================
struct CtOps { int k[30]; int a[30]; int b[30]; double th[30]; };

__host__ __device__ constexpr void ct_twist(uint32_t* mt) {
    for (int i = 0; i < 624; i++) {
        uint32_t y = (mt[i] & 0x80000000u) | (mt[(i + 1) % 624] & 0x7fffffffu);
        mt[i] = mt[(i + 397) % 624] ^ (y >> 1) ^ ((y & 1u) ? 0x9908b0dfu : 0u);
    }
}
__host__ __device__ constexpr uint32_t ct_next(uint32_t* mt, int& mti) {
    if (mti >= 624) { ct_twist(mt); mti = 0; }
    uint32_t y = mt[mti++];
    y ^= y >> 11;
    y ^= (y << 7) & 0x9d2c5680u;
    y ^= (y << 15) & 0xefc60000u;
    y ^= y >> 18;
    return y;
}
__host__ __device__ constexpr uint32_t ct_ri(uint32_t* mt, int& mti, uint32_t n) {
    uint32_t rng = n - 1u, mask = rng;
    mask |= mask >> 1; mask |= mask >> 2; mask |= mask >> 4;
    mask |= mask >> 8; mask |= mask >> 16;
    uint32_t v = ct_next(mt, mti) & mask;
    while (v > rng) v = ct_next(mt, mti) & mask;
    return v;
}
__host__ __device__ constexpr double ct_rs(uint32_t* mt, int& mti) {
    uint32_t a = ct_next(mt, mti) >> 5, b = ct_next(mt, mti) >> 6;
    return (a * 67108864.0 + b) * (1.0 / 9007199254740992.0);
}
__host__ __device__ constexpr CtOps ct_build() {
    uint32_t mt[624] = {};
    mt[0] = 1234u;
    for (int i = 1; i < 624; i++)
        mt[i] = 1812433253u * (mt[i - 1] ^ (mt[i - 1] >> 30)) + (uint32_t)i;
    int mti = 624;
    CtOps R{};
    const double TWO_PI = 6.283185307179586476925286766559;
    for (int t = 0; t < 30; t++) {
        uint32_t kind = ct_ri(mt, mti, 4u);
        if (kind == 3u) {
            int c = (int)ct_ri(mt, mti, 8u);
            int tt = (int)ct_ri(mt, mti, 7u);
            if (tt >= c) tt += 1;
            R.k[t] = 3; R.a[t] = c; R.b[t] = tt; R.th[t] = 0.0;
        } else {
            int w = (int)ct_ri(mt, mti, 8u);
            R.k[t] = (int)kind; R.a[t] = w; R.b[t] = 0;
            R.th[t] = TWO_PI * ct_rs(mt, mti);
        }
    }
    return R;
}
static constexpr CtOps OPS = ct_build();

__host__ __device__ constexpr double ct_cos(double x) {
    double t = 1.0, sum = 1.0;
    for (int k = 1; k <= 25; k++) { t *= -x * x / ((2.0 * k - 1.0) * (2.0 * k)); sum += t; }
    return sum;
}
__host__ __device__ constexpr double ct_sin(double x) {
    double t = x, sum = x;
    for (int k = 1; k <= 25; k++) { t *= -x * x / ((2.0 * k) * (2.0 * k + 1.0)); sum += t; }
    return sum;
}

struct Perm { int p[8]; };
__host__ __device__ constexpr Perm build_perm() {
    int score[8] = {};
    for (int t = 0; t < 30; t++) {
        if (OPS.k[t] == 3) { score[OPS.b[t]] += 2; score[OPS.a[t]] += 1; }
        else if (OPS.k[t] == 0 || OPS.k[t] == 1) score[OPS.a[t]] += 2;
    }
    Perm P{};
    bool used[8] = {};
    for (int r = 0; r < 3; r++) {
        int best = -1, bs = -1;
        for (int w = 0; w < 8; w++)
            if (!used[w] && score[w] > bs) { bs = score[w]; best = w; }
        used[best] = true;
        P.p[best] = r;
    }
    int nb = 3;
    for (int w = 0; w < 8; w++)
        if (!used[w]) P.p[w] = nb++;
    return P;
}
static constexpr Perm PB = build_perm();
template<int W> struct PBit { static constexpr int p = PB.p[W]; };

template<int T> struct OpK {
    static constexpr int   kind = OPS.k[T];
    static constexpr int   pa   = PB.p[OPS.a[T]];
    static constexpr int   pb   = PB.p[OPS.b[T]];
    static constexpr float thf  = (float)OPS.th[T];
    static constexpr float hf   = thf * 0.5f;
    static constexpr float c    = (float)ct_cos((double)hf);
    static constexpr float s    = (float)ct_sin((double)hf);
};

// ======================================================================
// scalar qfc gate primitives (proven)
// ======================================================================
template<int P>
__device__ __forceinline__ void rx_loc(float re[8], float im[8], float c, float s) {
#pragma unroll
    for (int e = 0; e < 8; e++) {
        if (e & (1 << P)) continue;
        int o = e | (1 << P);
        float a0r = re[e], a0i = im[e], a1r = re[o], a1i = im[o];
        re[e] = c * a0r + s * a1i; im[e] = c * a0i - s * a1r;
        re[o] = c * a1r + s * a0i; im[o] = c * a1i - s * a0r;
    }
}
template<int P>
__device__ __forceinline__ void ry_loc(float re[8], float im[8], float c, float s) {
#pragma unroll
    for (int e = 0; e < 8; e++) {
        if (e & (1 << P)) continue;
        int o = e | (1 << P);
        float a0r = re[e], a0i = im[e], a1r = re[o], a1i = im[o];
        re[e] = c * a0r - s * a1r; im[e] = c * a0i - s * a1i;
        re[o] = s * a0r + c * a1r; im[o] = s * a0i + c * a1i;
    }
}
__device__ __forceinline__ void rx_lane(float re[8], float im[8], float c, float s, int m) {
#pragma unroll
    for (int j = 0; j < 8; j++) {
        float orr = __shfl_xor_sync(FULLM, re[j], m);
        float oii = __shfl_xor_sync(FULLM, im[j], m);
        re[j] = c * re[j] + s * oii;
        im[j] = c * im[j] - s * orr;
    }
}
__device__ __forceinline__ void ry_lane(float re[8], float im[8], float c, float s, int m, int bit) {
    float t = bit ? s : -s;
#pragma unroll
    for (int j = 0; j < 8; j++) {
        float orr = __shfl_xor_sync(FULLM, re[j], m);
        float oii = __shfl_xor_sync(FULLM, im[j], m);
        re[j] = c * re[j] + t * orr;
        im[j] = c * im[j] + t * oii;
    }
}

template<int T>
__device__ __forceinline__ void apply_one(float re[8], float im[8], int lane) {
    constexpr int kind = OpK<T>::kind;
    constexpr float c = OpK<T>::c;
    constexpr float s = OpK<T>::s;
    if constexpr (kind == 3) {
        constexpr int pc = OpK<T>::pa;
        constexpr int pt = OpK<T>::pb;
        if constexpr (pt >= 3) {
            constexpr int m = 1 << (pt - 3);
            if constexpr (pc >= 3) {
                int ctrl = (lane >> (pc - 3)) & 1;
#pragma unroll
                for (int j = 0; j < 8; j++) {
                    float orr = __shfl_xor_sync(FULLM, re[j], m);
                    float oii = __shfl_xor_sync(FULLM, im[j], m);
                    re[j] = ctrl ? orr : re[j];
                    im[j] = ctrl ? oii : im[j];
                }
            } else {
#pragma unroll
                for (int j = 0; j < 8; j++) {
                    if ((j >> pc) & 1) {
                        re[j] = __shfl_xor_sync(FULLM, re[j], m);
                        im[j] = __shfl_xor_sync(FULLM, im[j], m);
                    }
                }
            }
        } else {
            constexpr int tm = 1 << pt;
            if constexpr (pc >= 3) {
                if ((lane >> (pc - 3)) & 1) {
#pragma unroll
                    for (int e = 0; e < 8; e++) {
                        if (e & tm) continue;
                        int o = e | tm;
                        float tr = re[e]; re[e] = re[o]; re[o] = tr;
                        float ti = im[e]; im[e] = im[o]; im[o] = ti;
                    }
                }
            } else {
#pragma unroll
                for (int e = 0; e < 8; e++) {
                    if ((e & tm) || !((e >> pc) & 1)) continue;
                    int o = e | tm;
                    float tr = re[e]; re[e] = re[o]; re[o] = tr;
                    float ti = im[e]; im[e] = im[o]; im[o] = ti;
                }
            }
        }
    } else if constexpr (kind == 2) {
        constexpr int p = OpK<T>::pa;
        if constexpr (p >= 3) {
            int bit = (lane >> (p - 3)) & 1;
            float t = bit ? -s : s;
            float tn = -t;
#pragma unroll
            for (int j = 0; j < 8; j++) {
                float r = re[j], i = im[j];
                re[j] = fmaf(t, i, c * r);
                im[j] = fmaf(tn, r, c * i);
            }
        } else {
#pragma unroll
            for (int j = 0; j < 8; j++) {
                float sg = ((j >> p) & 1) ? -s : s;
                float r = re[j], i = im[j];
                re[j] = fmaf(sg, i, c * r);
                im[j] = fmaf(-sg, r, c * i);
            }
        }
    } else if constexpr (kind == 0) {
        constexpr int p = OpK<T>::pa;
        if constexpr (p >= 3)      rx_lane(re, im, c, s, 1 << (p - 3));
        else if constexpr (p == 0) rx_loc<0>(re, im, c, s);
        else if constexpr (p == 1) rx_loc<1>(re, im, c, s);
        else                       rx_loc<2>(re, im, c, s);
    } else {
        constexpr int p = OpK<T>::pa;
        if constexpr (p >= 3)      ry_lane(re, im, c, s, 1 << (p - 3), (lane >> (p - 3)) & 1);
        else if constexpr (p == 0) ry_loc<0>(re, im, c, s);
        else if constexpr (p == 1) ry_loc<1>(re, im, c, s);
        else                       ry_loc<2>(re, im, c, s);
    }
}
template<int T>
__device__ __forceinline__ void apply_seq(float re[8], float im[8], int lane) {
    if constexpr (T < 30) {
        apply_one<T>(re, im, lane);
        apply_seq<T + 1>(re, im, lane);
    }
}

template<int W>
__device__ __forceinline__ void init_lane_factor(float& fr, const float cs[8],
                                                 const float sn[8], int lane) {
    if constexpr (W < 8) {
        constexpr int p = PBit<W>::p;
        if constexpr (p >= 3) {
            int bit = (lane >> (p - 3)) & 1;
            fr *= bit ? sn[W] : cs[W];
        }
        init_lane_factor<W + 1>(fr, cs, sn, lane);
    }
}
template<int J, int W>
__device__ __forceinline__ void reg_factor_acc(float& g, const float cs[8], const float sn[8]) {
    if constexpr (W < 8) {
        constexpr int p = PBit<W>::p;
        if constexpr (p < 3) {
            if constexpr (((J >> p) & 1) != 0) g *= sn[W];
            else                               g *= cs[W];
        }
        reg_factor_acc<J, W + 1>(g, cs, sn);
    }
}
template<int J>
__device__ __forceinline__ void init_amps(float re[8], float im[8], float fr,
                                          const float cs[8], const float sn[8]) {
    if constexpr (J < 8) {
        float g = fr;
        reg_factor_acc<J, 0>(g, cs, sn);
        re[J] = g;
        im[J] = 0.f;
        init_amps<J + 1>(re, im, fr, cs, sn);
    }
}

// ======================================================================
// measure with fused final-RX (Heisenberg): RX(th)† Z RX(th) = cos·Z + sin·Y,
// RX on other wires commutes with Z_w.  <Y_w> = 2 Σ_pairs Im(conj(a0)·a1).
// lane wires: per-lane signed partial s·Σ_j(re·p_im − im·p_re), s=+1 bit0 /
// −1 bit1, sums across lanes to exactly Y_w (each pair counted twice with
// matching sign).  reg wires need the explicit ×2.
// ======================================================================
template<int W>
__device__ __forceinline__ void measure_zy(float zp[8], const float re[8], const float im[8],
                                           const float pj[8], float tot,
                                           const float* __restrict__ phiq, int lane) {
    if constexpr (W < 8) {
        constexpr int p = PBit<W>::p;
        float snw, cw;
        __sincosf(phiq[W], &snw, &cw);           // FULL angle
        if constexpr (p >= 3) {
            constexpr int m = 1 << (p - 3);
            float y = 0.f;
#pragma unroll
            for (int j = 0; j < 8; j++) {
                float pr = __shfl_xor_sync(FULLM, re[j], m);
                float pi = __shfl_xor_sync(FULLM, im[j], m);
                y = fmaf(re[j], pi, y);
                y = fmaf(-im[j], pr, y);
            }
            float v = fmaf(snw, y, cw * tot);
            zp[W] = ((lane >> (p - 3)) & 1) ? -v : v;
        } else {
            constexpr int tm = 1 << p;
            float z = 0.f, y = 0.f;
#pragma unroll
            for (int e = 0; e < 8; e++) {
                if (e & tm) continue;
                int o = e | tm;
                z += pj[e] - pj[o];
                y = fmaf(re[e], im[o], y);
                y = fmaf(-im[e], re[o], y);
            }
            zp[W] = fmaf(cw, z, (2.f * snw) * y);
        }
        measure_zy<W + 1>(zp, re, im, pj, tot, phiq, lane);
    }
}

__device__ __forceinline__ float tanhfast(float x) {
    float y;
    asm("tanh.approx.f32 %0, %1;" : "=f"(y) : "f"(x));
    return y;
}

// ======================================================================
// kernel 1: embed + LSTM fused. 8 warps: wid7 = LSTM (hi-wid arbiter
// priority), wid0-6 = embed. One block per batch element. CH=32 (5 beats).
// ======================================================================
__global__ void __launch_bounds__(256) k_prod(
    const float* __restrict__ emb, const float* __restrict__ Win,
    const float* __restrict__ b_in, const float* __restrict__ phi,
    const float* __restrict__ Wout, const float* __restrict__ b_out,
    const long long* __restrict__ sent)
{
    __shared__ float sW[32 * 76];
    __shared__ float zbuf[2][CH][32];
    __shared__ int   s_is64;

    int tid = threadIdx.x;
    int wid = tid >> 5;
    int lane = tid & 31;
    int b = blockIdx.x;

    for (int i = tid; i < 32 * 72; i += 256) {
        int r = i / 72, f = i - r * 72;
        sW[r * 76 + f] = Win[i];
    }
    if (tid == 0) {
        int cnt = 0;
        for (int i = 0; i < 8; i++) {
            long long v = sent[i];
            cnt += (v >= 0 && v < V_SZ);
        }
        s_is64 = (cnt >= 5);
    }
    __syncthreads();
    bool is64 = (s_is64 != 0);

    float Wh[8], Wo[8], bphi = 0.f, bo = 0.f, hn = 0.f, cst = 0.f;
    int hh = 0, basem = 0; bool isg = false;
    if (wid == LSTM_WID) {
#pragma unroll
        for (int j = 0; j < 8; j++) Wh[j] = sW[lane * 76 + 64 + j];
#pragma unroll
        for (int j = 0; j < 8; j++) Wo[j] = Wout[lane * 8 + j];
        bphi = b_in[lane] + phi[lane];
        bo = b_out[lane];
        hh = lane & 7; basem = lane & 24; isg = (basem == 16);
    }

    for (int i = 0; i <= NCH; i++) {
        if (wid != LSTM_WID) {
            int ce = i;
            if (ce < NCH) {
                for (int t = wid; t < CH; t += NEMB) {
                    int s = ce * CH + t;
                    long long tok = is64 ? sent[s * B_SZ + b]
                                         : (long long)(((const int*)sent)[s * B_SZ + b]);
                    const float4* er = reinterpret_cast<const float4*>(emb + (size_t)tok * E_DIM);
                    const float4* wr = reinterpret_cast<const float4*>(&sW[lane * 76]);
                    float a0 = 0.f, a1 = 0.f, a2 = 0.f, a3 = 0.f;
#pragma unroll
                    for (int k = 0; k < 16; k++) {
                        float4 e4 = er[k];
                        float4 w4 = wr[k];
                        a0 = fmaf(e4.x, w4.x, a0); a1 = fmaf(e4.y, w4.y, a1);
                        a2 = fmaf(e4.z, w4.z, a2); a3 = fmaf(e4.w, w4.w, a3);
                    }
                    zbuf[ce & 1][t][lane] = (a0 + a1) + (a2 + a3);
                }
            }
        } else {
            int cl = i - 1;
            if (cl >= 0) {
                float zt[CH];
#pragma unroll
                for (int t = 0; t < CH; t++) zt[t] = zbuf[cl & 1][t][lane];
#pragma unroll 1
                for (int t = 0; t < CH; t++) {
                    float za = zt[t] + bphi, zb = 0.f;
#pragma unroll
                    for (int j = 0; j < 4; j++) {
                        za = fmaf(Wh[j],     __shfl_sync(FULLM, hn, j),     za);
                        zb = fmaf(Wh[j + 4], __shfl_sync(FULLM, hn, j + 4), zb);
                    }
                    float myc = __cosf(za + zb);
                    float cj[8];
#pragma unroll
                    for (int j = 0; j < 8; j++) cj[j] = __shfl_sync(FULLM, myc, basem + j);
                    // split-Horner: pre = (bo + A-chain) + P4 * B-chain
                    float tA = Wo[3];
                    tA = fmaf(cj[3], tA, Wo[2]);
                    tA = fmaf(cj[2], tA, Wo[1]);
                    tA = fmaf(cj[1], tA, Wo[0]);
                    float Ab = fmaf(cj[0], tA, bo);
                    float tB = Wo[7];
                    tB = fmaf(cj[7], tB, Wo[6]);
                    tB = fmaf(cj[6], tB, Wo[5]);
                    tB = fmaf(cj[5], tB, Wo[4]);
                    float Bv = cj[4] * tB;
                    float P4 = (cj[0] * cj[1]) * (cj[2] * cj[3]);
                    float pre = fmaf(P4, Bv, Ab);
                    float arg = isg ? pre : 0.5f * pre;
                    float ta = tanhfast(arg);
                    float a = isg ? ta : fmaf(0.5f, ta, 0.5f);
                    float vf = __shfl_sync(FULLM, a, hh);
                    float vi = __shfl_sync(FULLM, a, 8 + hh);
                    float vg = __shfl_sync(FULLM, a, 16 + hh);
                    float vo = __shfl_sync(FULLM, a, 24 + hh);
                    cst = fmaf(vf, cst, vi * vg);
                    hn = vo * tanhfast(cst);
                    if (lane < 8) g_h[(b * S_LEN + cl * CH + t) * H_DIM + lane] = hn;
                }
            }
        }
        __syncthreads();
    }
}

// ======================================================================
// kernel 2: QFC statevector head — final-RX fused into measurement
// ======================================================================
__global__ void __launch_bounds__(256) k_qfc(const float* __restrict__ phiq,
                                             const float* __restrict__ Whead,
                                             const float* __restrict__ b_head,
                                             float* __restrict__ out) {
    int warp = (blockIdx.x * blockDim.x + threadIdx.x) >> 5;
    int lane = threadIdx.x & 31;

    float re[8], im[8];
    {
        float cs[8], sn[8];
#pragma unroll
        for (int w = 0; w < 8; w++) {
            __sincosf(0.5f * g_h[warp * 8 + w], &sn[w], &cs[w]);
        }
        float fr = 1.f;
        init_lane_factor<0>(fr, cs, sn, lane);
        init_amps<0>(re, im, fr, cs, sn);
    }

    apply_seq<0>(re, im, lane);

    // measure with final RX folded into the observable
    float pj[8];
    float tot = 0.f;
#pragma unroll
    for (int j = 0; j < 8; j++) {
        pj[j] = re[j] * re[j] + im[j] * im[j];
        tot += pj[j];
    }
    float zp[8];
    measure_zy<0>(zp, re, im, pj, tot, phiq, lane);
#pragma unroll
    for (int off = 16; off >= 1; off >>= 1) {
#pragma unroll
        for (int w = 0; w < 8; w++) zp[w] += __shfl_xor_sync(FULLM, zp[w], off);
    }

    float logit = __int_as_float(0xff800000);
    if (lane < T_OUT) {
        float a = b_head[lane];
#pragma unroll
        for (int h = 0; h < 8; h++) a += zp[h] * Whead[lane * 8 + h];
        logit = a;
    }
    float m = logit;
#pragma unroll
    for (int off = 16; off >= 1; off >>= 1) m = fmaxf(m, __shfl_xor_sync(FULLM, m, off));
    float e = (lane < T_OUT) ? __expf(logit - m) : 0.f;
#pragma unroll
    for (int off = 16; off >= 1; off >>= 1) e += __shfl_xor_sync(FULLM, e, off);
    if (lane < T_OUT) out[warp * T_OUT + lane] = logit - m - __logf(e);
}

// ======================================================================
extern "C" void kernel_launch(void* const* d_in, const int* in_sizes, int n_in,
                              void* d_out, int out_size) {
    const float* emb     = (const float*)d_in[0];
    const float* Win     = (const float*)d_in[1];
    const float* b_in    = (const float*)d_in[2];
    const float* phi     = (const float*)d_in[3];
    const float* Wout    = (const float*)d_in[4];
    const float* b_out   = (const float*)d_in[5];
    const float* phiq    = (const float*)d_in[6];
    const float* Whead   = (const float*)d_in[7];
    const float* b_head  = (const float*)d_in[8];
    const long long* sent = (const long long*)d_in[9];
    float* out = (float*)d_out;

    k_prod<<<B_SZ, 256>>>(emb, Win, b_in, phi, Wout, b_out, sent);
    k_qfc<<<NSAMP / 8, 256>>>(phiq, Whead, b_head, out);
}

// round 14
// speedup vs baseline: 1.0940x; 1.0940x over previous
#include <cuda_runtime.h>
#include <cstdint>
#include <math.h>

#define S_LEN 128
#define B_SZ  128
#define E_DIM 64
#define H_DIM 8
#define V_SZ  30000
#define T_OUT 12
#define NSAMP (S_LEN * B_SZ)
#define FULLM 0xffffffffu
#define CH    16
#define NCH   (S_LEN / CH)
#define LSTM_WID 7          // highest wid -> arbiter priority
#define NEMB  7             // embed warps 0..6

// ---------------- device scratch ----------------
__device__ float g_h[NSAMP * H_DIM];   // row n = b*S_LEN + s

// ======================================================================
// Compile-time numpy legacy RandomState(1234) replica -> fixed gate list
// ======================================================================
struct CtOps { int k[30]; int a[30]; int b[30]; double th[30]; };

__host__ __device__ constexpr void ct_twist(uint32_t* mt) {
    for (int i = 0; i < 624; i++) {
        uint32_t y = (mt[i] & 0x80000000u) | (mt[(i + 1) % 624] & 0x7fffffffu);
        mt[i] = mt[(i + 397) % 624] ^ (y >> 1) ^ ((y & 1u) ? 0x9908b0dfu : 0u);
    }
}
__host__ __device__ constexpr uint32_t ct_next(uint32_t* mt, int& mti) {
    if (mti >= 624) { ct_twist(mt); mti = 0; }
    uint32_t y = mt[mti++];
    y ^= y >> 11;
    y ^= (y << 7) & 0x9d2c5680u;
    y ^= (y << 15) & 0xefc60000u;
    y ^= y >> 18;
    return y;
}
__host__ __device__ constexpr uint32_t ct_ri(uint32_t* mt, int& mti, uint32_t n) {
    uint32_t rng = n - 1u, mask = rng;
    mask |= mask >> 1; mask |= mask >> 2; mask |= mask >> 4;
    mask |= mask >> 8; mask |= mask >> 16;
    uint32_t v = ct_next(mt, mti) & mask;
    while (v > rng) v = ct_next(mt, mti) & mask;
    return v;
}
__host__ __device__ constexpr double ct_rs(uint32_t* mt, int& mti) {
    uint32_t a = ct_next(mt, mti) >> 5, b = ct_next(mt, mti) >> 6;
    return (a * 67108864.0 + b) * (1.0 / 9007199254740992.0);
}
__host__ __device__ constexpr CtOps ct_build() {
    uint32_t mt[624] = {};
    mt[0] = 1234u;
    for (int i = 1; i < 624; i++)
        mt[i] = 1812433253u * (mt[i - 1] ^ (mt[i - 1] >> 30)) + (uint32_t)i;
    int mti = 624;
    CtOps R{};
    const double TWO_PI = 6.283185307179586476925286766559;
    for (int t = 0; t < 30; t++) {
        uint32_t kind = ct_ri(mt, mti, 4u);
        if (kind == 3u) {
            int c = (int)ct_ri(mt, mti, 8u);
            int tt = (int)ct_ri(mt, mti, 7u);
            if (tt >= c) tt += 1;
            R.k[t] = 3; R.a[t] = c; R.b[t] = tt; R.th[t] = 0.0;
        } else {
            int w = (int)ct_ri(mt, mti, 8u);
            R.k[t] = (int)kind; R.a[t] = w; R.b[t] = 0;
            R.th[t] = TWO_PI * ct_rs(mt, mti);
        }
    }
    return R;
}
static constexpr CtOps OPS = ct_build();

__host__ __device__ constexpr double ct_cos(double x) {
    double t = 1.0, sum = 1.0;
    for (int k = 1; k <= 25; k++) { t *= -x * x / ((2.0 * k - 1.0) * (2.0 * k)); sum += t; }
    return sum;
}
__host__ __device__ constexpr double ct_sin(double x) {
    double t = x, sum = x;
    for (int k = 1; k <= 25; k++) { t *= -x * x / ((2.0 * k) * (2.0 * k + 1.0)); sum += t; }
    return sum;
}

struct Perm { int p[8]; };
__host__ __device__ constexpr Perm build_perm() {
    int score[8] = {};
    for (int t = 0; t < 30; t++) {
        if (OPS.k[t] == 3) { score[OPS.b[t]] += 2; score[OPS.a[t]] += 1; }
        else if (OPS.k[t] == 0 || OPS.k[t] == 1) score[OPS.a[t]] += 2;
    }
    Perm P{};
    bool used[8] = {};
    for (int r = 0; r < 3; r++) {
        int best = -1, bs = -1;
        for (int w = 0; w < 8; w++)
            if (!used[w] && score[w] > bs) { bs = score[w]; best = w; }
        used[best] = true;
        P.p[best] = r;
    }
    int nb = 3;
    for (int w = 0; w < 8; w++)
        if (!used[w]) P.p[w] = nb++;
    return P;
}
static constexpr Perm PB = build_perm();
template<int W> struct PBit { static constexpr int p = PB.p[W]; };

template<int T> struct OpK {
    static constexpr int   kind = OPS.k[T];
    static constexpr int   pa   = PB.p[OPS.a[T]];
    static constexpr int   pb   = PB.p[OPS.b[T]];
    static constexpr float thf  = (float)OPS.th[T];
    static constexpr float hf   = thf * 0.5f;
    static constexpr float c    = (float)ct_cos((double)hf);
    static constexpr float s    = (float)ct_sin((double)hf);
};

// ======================================================================
// scalar qfc gate primitives (proven)
// ======================================================================
template<int P>
__device__ __forceinline__ void rx_loc(float re[8], float im[8], float c, float s) {
#pragma unroll
    for (int e = 0; e < 8; e++) {
        if (e & (1 << P)) continue;
        int o = e | (1 << P);
        float a0r = re[e], a0i = im[e], a1r = re[o], a1i = im[o];
        re[e] = c * a0r + s * a1i; im[e] = c * a0i - s * a1r;
        re[o] = c * a1r + s * a0i; im[o] = c * a1i - s * a0r;
    }
}
template<int P>
__device__ __forceinline__ void ry_loc(float re[8], float im[8], float c, float s) {
#pragma unroll
    for (int e = 0; e < 8; e++) {
        if (e & (1 << P)) continue;
        int o = e | (1 << P);
        float a0r = re[e], a0i = im[e], a1r = re[o], a1i = im[o];
        re[e] = c * a0r - s * a1r; im[e] = c * a0i - s * a1i;
        re[o] = s * a0r + c * a1r; im[o] = s * a0i + c * a1i;
    }
}
__device__ __forceinline__ void rx_lane(float re[8], float im[8], float c, float s, int m) {
#pragma unroll
    for (int j = 0; j < 8; j++) {
        float orr = __shfl_xor_sync(FULLM, re[j], m);
        float oii = __shfl_xor_sync(FULLM, im[j], m);
        re[j] = c * re[j] + s * oii;
        im[j] = c * im[j] - s * orr;
    }
}
__device__ __forceinline__ void ry_lane(float re[8], float im[8], float c, float s, int m, int bit) {
    float t = bit ? s : -s;
#pragma unroll
    for (int j = 0; j < 8; j++) {
        float orr = __shfl_xor_sync(FULLM, re[j], m);
        float oii = __shfl_xor_sync(FULLM, im[j], m);
        re[j] = c * re[j] + t * orr;
        im[j] = c * im[j] + t * oii;
    }
}

template<int T>
__device__ __forceinline__ void apply_one(float re[8], float im[8], int lane) {
    constexpr int kind = OpK<T>::kind;
    constexpr float c = OpK<T>::c;
    constexpr float s = OpK<T>::s;
    if constexpr (kind == 3) {
        constexpr int pc = OpK<T>::pa;
        constexpr int pt = OpK<T>::pb;
        if constexpr (pt >= 3) {
            constexpr int m = 1 << (pt - 3);
            if constexpr (pc >= 3) {
                int ctrl = (lane >> (pc - 3)) & 1;
#pragma unroll
                for (int j = 0; j < 8; j++) {
                    float orr = __shfl_xor_sync(FULLM, re[j], m);
                    float oii = __shfl_xor_sync(FULLM, im[j], m);
                    re[j] = ctrl ? orr : re[j];
                    im[j] = ctrl ? oii : im[j];
                }
            } else {
#pragma unroll
                for (int j = 0; j < 8; j++) {
                    if ((j >> pc) & 1) {
                        re[j] = __shfl_xor_sync(FULLM, re[j], m);
                        im[j] = __shfl_xor_sync(FULLM, im[j], m);
                    }
                }
            }
        } else {
            constexpr int tm = 1 << pt;
            if constexpr (pc >= 3) {
                if ((lane >> (pc - 3)) & 1) {
#pragma unroll
                    for (int e = 0; e < 8; e++) {
                        if (e & tm) continue;
                        int o = e | tm;
                        float tr = re[e]; re[e] = re[o]; re[o] = tr;
                        float ti = im[e]; im[e] = im[o]; im[o] = ti;
                    }
                }
            } else {
#pragma unroll
                for (int e = 0; e < 8; e++) {
                    if ((e & tm) || !((e >> pc) & 1)) continue;
                    int o = e | tm;
                    float tr = re[e]; re[e] = re[o]; re[o] = tr;
                    float ti = im[e]; im[e] = im[o]; im[o] = ti;
                }
            }
        }
    } else if constexpr (kind == 2) {
        constexpr int p = OpK<T>::pa;
        if constexpr (p >= 3) {
            int bit = (lane >> (p - 3)) & 1;
            float t = bit ? -s : s;
            float tn = -t;
#pragma unroll
            for (int j = 0; j < 8; j++) {
                float r = re[j], i = im[j];
                re[j] = fmaf(t, i, c * r);
                im[j] = fmaf(tn, r, c * i);
            }
        } else {
#pragma unroll
            for (int j = 0; j < 8; j++) {
                float sg = ((j >> p) & 1) ? -s : s;
                float r = re[j], i = im[j];
                re[j] = fmaf(sg, i, c * r);
                im[j] = fmaf(-sg, r, c * i);
            }
        }
    } else if constexpr (kind == 0) {
        constexpr int p = OpK<T>::pa;
        if constexpr (p >= 3)      rx_lane(re, im, c, s, 1 << (p - 3));
        else if constexpr (p == 0) rx_loc<0>(re, im, c, s);
        else if constexpr (p == 1) rx_loc<1>(re, im, c, s);
        else                       rx_loc<2>(re, im, c, s);
    } else {
        constexpr int p = OpK<T>::pa;
        if constexpr (p >= 3)      ry_lane(re, im, c, s, 1 << (p - 3), (lane >> (p - 3)) & 1);
        else if constexpr (p == 0) ry_loc<0>(re, im, c, s);
        else if constexpr (p == 1) ry_loc<1>(re, im, c, s);
        else                       ry_loc<2>(re, im, c, s);
    }
}
template<int T>
__device__ __forceinline__ void apply_seq(float re[8], float im[8], int lane) {
    if constexpr (T < 30) {
        apply_one<T>(re, im, lane);
        apply_seq<T + 1>(re, im, lane);
    }
}

template<int W>
__device__ __forceinline__ void init_lane_factor(float& fr, const float cs[8],
                                                 const float sn[8], int lane) {
    if constexpr (W < 8) {
        constexpr int p = PBit<W>::p;
        if constexpr (p >= 3) {
            int bit = (lane >> (p - 3)) & 1;
            fr *= bit ? sn[W] : cs[W];
        }
        init_lane_factor<W + 1>(fr, cs, sn, lane);
    }
}
template<int J, int W>
__device__ __forceinline__ void reg_factor_acc(float& g, const float cs[8], const float sn[8]) {
    if constexpr (W < 8) {
        constexpr int p = PBit<W>::p;
        if constexpr (p < 3) {
            if constexpr (((J >> p) & 1) != 0) g *= sn[W];
            else                               g *= cs[W];
        }
        reg_factor_acc<J, W + 1>(g, cs, sn);
    }
}
template<int J>
__device__ __forceinline__ void init_amps(float re[8], float im[8], float fr,
                                          const float cs[8], const float sn[8]) {
    if constexpr (J < 8) {
        float g = fr;
        reg_factor_acc<J, 0>(g, cs, sn);
        re[J] = g;
        im[J] = 0.f;
        init_amps<J + 1>(re, im, fr, cs, sn);
    }
}

// ======================================================================
// measure with fused final-RX (Heisenberg): RX(th)† Z RX(th) = cos·Z + sin·Y
// (proven in round 13, rel_err 1.03e-7)
// ======================================================================
template<int W>
__device__ __forceinline__ void measure_zy(float zp[8], const float re[8], const float im[8],
                                           const float pj[8], float tot,
                                           const float* __restrict__ phiq, int lane) {
    if constexpr (W < 8) {
        constexpr int p = PBit<W>::p;
        float snw, cw;
        __sincosf(phiq[W], &snw, &cw);           // FULL angle
        if constexpr (p >= 3) {
            constexpr int m = 1 << (p - 3);
            float y = 0.f;
#pragma unroll
            for (int j = 0; j < 8; j++) {
                float pr = __shfl_xor_sync(FULLM, re[j], m);
                float pi = __shfl_xor_sync(FULLM, im[j], m);
                y = fmaf(re[j], pi, y);
                y = fmaf(-im[j], pr, y);
            }
            float v = fmaf(snw, y, cw * tot);
            zp[W] = ((lane >> (p - 3)) & 1) ? -v : v;
        } else {
            constexpr int tm = 1 << p;
            float z = 0.f, y = 0.f;
#pragma unroll
            for (int e = 0; e < 8; e++) {
                if (e & tm) continue;
                int o = e | tm;
                z += pj[e] - pj[o];
                y = fmaf(re[e], im[o], y);
                y = fmaf(-im[e], re[o], y);
            }
            zp[W] = fmaf(cw, z, (2.f * snw) * y);
        }
        measure_zy<W + 1>(zp, re, im, pj, tot, phiq, lane);
    }
}

__device__ __forceinline__ float tanhfast(float x) {
    float y;
    asm("tanh.approx.f32 %0, %1;" : "=f"(y) : "f"(x));
    return y;
}

// ======================================================================
// kernel 1: embed + LSTM fused (round-12 proven, CH=16). 8 warps:
// wid7 = LSTM (hi-wid arbiter priority), wid0-6 = embed.
// Chain tweak: 0.5x folded into Wo/bo for sigmoid lanes (exact algebra).
// ======================================================================
__global__ void __launch_bounds__(256) k_prod(
    const float* __restrict__ emb, const float* __restrict__ Win,
    const float* __restrict__ b_in, const float* __restrict__ phi,
    const float* __restrict__ Wout, const float* __restrict__ b_out,
    const long long* __restrict__ sent)
{
    __shared__ float sW[32 * 76];
    __shared__ float zbuf[2][CH][32];
    __shared__ int   s_is64;

    int tid = threadIdx.x;
    int wid = tid >> 5;
    int lane = tid & 31;
    int b = blockIdx.x;

    for (int i = tid; i < 32 * 72; i += 256) {
        int r = i / 72, f = i - r * 72;
        sW[r * 76 + f] = Win[i];
    }
    if (tid == 0) {
        int cnt = 0;
        for (int i = 0; i < 8; i++) {
            long long v = sent[i];
            cnt += (v >= 0 && v < V_SZ);
        }
        s_is64 = (cnt >= 5);
    }
    __syncthreads();
    bool is64 = (s_is64 != 0);

    float Wh[8], Wo[8], bphi = 0.f, bo = 0.f, hn = 0.f, cst = 0.f;
    int hh = 0, basem = 0; bool isg = false;
    if (wid == LSTM_WID) {
        basem = lane & 24; isg = (basem == 16);
        float sc = isg ? 1.f : 0.5f;     // fold sigmoid's x/2 into weights
#pragma unroll
        for (int j = 0; j < 8; j++) Wh[j] = sW[lane * 76 + 64 + j];
#pragma unroll
        for (int j = 0; j < 8; j++) Wo[j] = sc * Wout[lane * 8 + j];
        bphi = b_in[lane] + phi[lane];
        bo = sc * b_out[lane];
        hh = lane & 7;
    }

    for (int i = 0; i <= NCH; i++) {
        if (wid != LSTM_WID) {
            int ce = i;
            if (ce < NCH) {
                for (int t = wid; t < CH; t += NEMB) {
                    int s = ce * CH + t;
                    long long tok = is64 ? sent[s * B_SZ + b]
                                         : (long long)(((const int*)sent)[s * B_SZ + b]);
                    const float4* er = reinterpret_cast<const float4*>(emb + (size_t)tok * E_DIM);
                    const float4* wr = reinterpret_cast<const float4*>(&sW[lane * 76]);
                    float a0 = 0.f, a1 = 0.f, a2 = 0.f, a3 = 0.f;
#pragma unroll
                    for (int k = 0; k < 16; k++) {
                        float4 e4 = er[k];
                        float4 w4 = wr[k];
                        a0 = fmaf(e4.x, w4.x, a0); a1 = fmaf(e4.y, w4.y, a1);
                        a2 = fmaf(e4.z, w4.z, a2); a3 = fmaf(e4.w, w4.w, a3);
                    }
                    zbuf[ce & 1][t][lane] = (a0 + a1) + (a2 + a3);
                }
            }
        } else {
            int cl = i - 1;
            if (cl >= 0) {
                float zt[CH];
#pragma unroll
                for (int t = 0; t < CH; t++) zt[t] = zbuf[cl & 1][t][lane];
#pragma unroll 1
                for (int t = 0; t < CH; t++) {
                    float za = zt[t] + bphi, zb = 0.f;
#pragma unroll
                    for (int j = 0; j < 4; j++) {
                        za = fmaf(Wh[j],     __shfl_sync(FULLM, hn, j),     za);
                        zb = fmaf(Wh[j + 4], __shfl_sync(FULLM, hn, j + 4), zb);
                    }
                    float myc = __cosf(za + zb);
                    float cj[8];
#pragma unroll
                    for (int j = 0; j < 8; j++) cj[j] = __shfl_sync(FULLM, myc, basem + j);
                    // split-Horner: arg = (bo + A-chain) + P4 * B-chain
                    // (Wo/bo prescaled by 0.5 for sigmoid lanes -> arg directly)
                    float tA = Wo[3];
                    tA = fmaf(cj[3], tA, Wo[2]);
                    tA = fmaf(cj[2], tA, Wo[1]);
                    tA = fmaf(cj[1], tA, Wo[0]);
                    float Ab = fmaf(cj[0], tA, bo);
                    float tB = Wo[7];
                    tB = fmaf(cj[7], tB, Wo[6]);
                    tB = fmaf(cj[6], tB, Wo[5]);
                    tB = fmaf(cj[5], tB, Wo[4]);
                    float Bv = cj[4] * tB;
                    float P4 = (cj[0] * cj[1]) * (cj[2] * cj[3]);
                    float arg = fmaf(P4, Bv, Ab);
                    float ta = tanhfast(arg);
                    float a = isg ? ta : fmaf(0.5f, ta, 0.5f);
                    float vf = __shfl_sync(FULLM, a, hh);
                    float vi = __shfl_sync(FULLM, a, 8 + hh);
                    float vg = __shfl_sync(FULLM, a, 16 + hh);
                    float vo = __shfl_sync(FULLM, a, 24 + hh);
                    cst = fmaf(vf, cst, vi * vg);
                    hn = vo * tanhfast(cst);
                    if (lane < 8) g_h[(b * S_LEN + cl * CH + t) * H_DIM + lane] = hn;
                }
            }
        }
        __syncthreads();
    }
}

// ======================================================================
// kernel 2: QFC statevector head — Heisenberg-fused final RX (round-13)
// ======================================================================
__global__ void __launch_bounds__(256) k_qfc(const float* __restrict__ phiq,
                                             const float* __restrict__ Whead,
                                             const float* __restrict__ b_head,
                                             float* __restrict__ out) {
    int warp = (blockIdx.x * blockDim.x + threadIdx.x) >> 5;
    int lane = threadIdx.x & 31;

    float re[8], im[8];
    {
        float cs[8], sn[8];
#pragma unroll
        for (int w = 0; w < 8; w++) {
            __sincosf(0.5f * g_h[warp * 8 + w], &sn[w], &cs[w]);
        }
        float fr = 1.f;
        init_lane_factor<0>(fr, cs, sn, lane);
        init_amps<0>(re, im, fr, cs, sn);
    }

    apply_seq<0>(re, im, lane);

    float pj[8];
    float tot = 0.f;
#pragma unroll
    for (int j = 0; j < 8; j++) {
        pj[j] = re[j] * re[j] + im[j] * im[j];
        tot += pj[j];
    }
    float zp[8];
    measure_zy<0>(zp, re, im, pj, tot, phiq, lane);
#pragma unroll
    for (int off = 16; off >= 1; off >>= 1) {
#pragma unroll
        for (int w = 0; w < 8; w++) zp[w] += __shfl_xor_sync(FULLM, zp[w], off);
    }

    float logit = __int_as_float(0xff800000);
    if (lane < T_OUT) {
        float a = b_head[lane];
#pragma unroll
        for (int h = 0; h < 8; h++) a += zp[h] * Whead[lane * 8 + h];
        logit = a;
    }
    float m = logit;
#pragma unroll
    for (int off = 16; off >= 1; off >>= 1) m = fmaxf(m, __shfl_xor_sync(FULLM, m, off));
    float e = (lane < T_OUT) ? __expf(logit - m) : 0.f;
#pragma unroll
    for (int off = 16; off >= 1; off >>= 1) e += __shfl_xor_sync(FULLM, e, off);
    if (lane < T_OUT) out[warp * T_OUT + lane] = logit - m - __logf(e);
}

// ======================================================================
extern "C" void kernel_launch(void* const* d_in, const int* in_sizes, int n_in,
                              void* d_out, int out_size) {
    const float* emb     = (const float*)d_in[0];
    const float* Win     = (const float*)d_in[1];
    const float* b_in    = (const float*)d_in[2];
    const float* phi     = (const float*)d_in[3];
    const float* Wout    = (const float*)d_in[4];
    const float* b_out   = (const float*)d_in[5];
    const float* phiq    = (const float*)d_in[6];
    const float* Whead   = (const float*)d_in[7];
    const float* b_head  = (const float*)d_in[8];
    const long long* sent = (const long long*)d_in[9];
    float* out = (float*)d_out;

    k_prod<<<B_SZ, 256>>>(emb, Win, b_in, phi, Wout, b_out, sent);
    k_qfc<<<NSAMP / 8, 256>>>(phiq, Whead, b_head, out);
}

// round 15
// speedup vs baseline: 1.1097x; 1.0143x over previous
#include <cuda_runtime.h>
#include <cstdint>
#include <math.h>

#define S_LEN 128
#define B_SZ  128
#define E_DIM 64
#define H_DIM 8
#define V_SZ  30000
#define T_OUT 12
#define NSAMP (S_LEN * B_SZ)
#define FULLM 0xffffffffu
#define CH    16
#define NCH   (S_LEN / CH)
#define LSTM_WID 7          // highest wid -> arbiter priority
#define NEMB  7             // embed warps 0..6

// ---------------- device scratch ----------------
__device__ float g_h[NSAMP * H_DIM];   // row n = b*S_LEN + s

// ======================================================================
// Compile-time numpy legacy RandomState(1234) replica -> fixed gate list
// ======================================================================
struct CtOps { int k[30]; int a[30]; int b[30]; double th[30]; };

__host__ __device__ constexpr void ct_twist(uint32_t* mt) {
    for (int i = 0; i < 624; i++) {
        uint32_t y = (mt[i] & 0x80000000u) | (mt[(i + 1) % 624] & 0x7fffffffu);
        mt[i] = mt[(i + 397) % 624] ^ (y >> 1) ^ ((y & 1u) ? 0x9908b0dfu : 0u);
    }
}
__host__ __device__ constexpr uint32_t ct_next(uint32_t* mt, int& mti) {
    if (mti >= 624) { ct_twist(mt); mti = 0; }
    uint32_t y = mt[mti++];
    y ^= y >> 11;
    y ^= (y << 7) & 0x9d2c5680u;
    y ^= (y << 15) & 0xefc60000u;
    y ^= y >> 18;
    return y;
}
__host__ __device__ constexpr uint32_t ct_ri(uint32_t* mt, int& mti, uint32_t n) {
    uint32_t rng = n - 1u, mask = rng;
    mask |= mask >> 1; mask |= mask >> 2; mask |= mask >> 4;
    mask |= mask >> 8; mask |= mask >> 16;
    uint32_t v = ct_next(mt, mti) & mask;
    while (v > rng) v = ct_next(mt, mti) & mask;
    return v;
}
__host__ __device__ constexpr double ct_rs(uint32_t* mt, int& mti) {
    uint32_t a = ct_next(mt, mti) >> 5, b = ct_next(mt, mti) >> 6;
    return (a * 67108864.0 + b) * (1.0 / 9007199254740992.0);
}
__host__ __device__ constexpr CtOps ct_build() {
    uint32_t mt[624] = {};
    mt[0] = 1234u;
    for (int i = 1; i < 624; i++)
        mt[i] = 1812433253u * (mt[i - 1] ^ (mt[i - 1] >> 30)) + (uint32_t)i;
    int mti = 624;
    CtOps R{};
    const double TWO_PI = 6.283185307179586476925286766559;
    for (int t = 0; t < 30; t++) {
        uint32_t kind = ct_ri(mt, mti, 4u);
        if (kind == 3u) {
            int c = (int)ct_ri(mt, mti, 8u);
            int tt = (int)ct_ri(mt, mti, 7u);
            if (tt >= c) tt += 1;
            R.k[t] = 3; R.a[t] = c; R.b[t] = tt; R.th[t] = 0.0;
        } else {
            int w = (int)ct_ri(mt, mti, 8u);
            R.k[t] = (int)kind; R.a[t] = w; R.b[t] = 0;
            R.th[t] = TWO_PI * ct_rs(mt, mti);
        }
    }
    return R;
}
static constexpr CtOps OPS = ct_build();

__host__ __device__ constexpr double ct_cos(double x) {
    double t = 1.0, sum = 1.0;
    for (int k = 1; k <= 25; k++) { t *= -x * x / ((2.0 * k - 1.0) * (2.0 * k)); sum += t; }
    return sum;
}
__host__ __device__ constexpr double ct_sin(double x) {
    double t = x, sum = x;
    for (int k = 1; k <= 25; k++) { t *= -x * x / ((2.0 * k) * (2.0 * k + 1.0)); sum += t; }
    return sum;
}

struct Perm { int p[8]; };
__host__ __device__ constexpr Perm build_perm() {
    int score[8] = {};
    for (int t = 0; t < 30; t++) {
        if (OPS.k[t] == 3) { score[OPS.b[t]] += 2; score[OPS.a[t]] += 1; }
        else if (OPS.k[t] == 0 || OPS.k[t] == 1) score[OPS.a[t]] += 2;
    }
    Perm P{};
    bool used[8] = {};
    for (int r = 0; r < 3; r++) {
        int best = -1, bs = -1;
        for (int w = 0; w < 8; w++)
            if (!used[w] && score[w] > bs) { bs = score[w]; best = w; }
        used[best] = true;
        P.p[best] = r;
    }
    int nb = 3;
    for (int w = 0; w < 8; w++)
        if (!used[w]) P.p[w] = nb++;
    return P;
}
static constexpr Perm PB = build_perm();
template<int W> struct PBit { static constexpr int p = PB.p[W]; };

template<int T> struct OpK {
    static constexpr int   kind = OPS.k[T];
    static constexpr int   pa   = PB.p[OPS.a[T]];
    static constexpr int   pb   = PB.p[OPS.b[T]];
    static constexpr float thf  = (float)OPS.th[T];
    static constexpr float hf   = thf * 0.5f;
    static constexpr float c    = (float)ct_cos((double)hf);
    static constexpr float s    = (float)ct_sin((double)hf);
};

// ======================================================================
// scalar qfc gate primitives (proven)
// ======================================================================
template<int P>
__device__ __forceinline__ void rx_loc(float re[8], float im[8], float c, float s) {
#pragma unroll
    for (int e = 0; e < 8; e++) {
        if (e & (1 << P)) continue;
        int o = e | (1 << P);
        float a0r = re[e], a0i = im[e], a1r = re[o], a1i = im[o];
        re[e] = c * a0r + s * a1i; im[e] = c * a0i - s * a1r;
        re[o] = c * a1r + s * a0i; im[o] = c * a1i - s * a0r;
    }
}
template<int P>
__device__ __forceinline__ void ry_loc(float re[8], float im[8], float c, float s) {
#pragma unroll
    for (int e = 0; e < 8; e++) {
        if (e & (1 << P)) continue;
        int o = e | (1 << P);
        float a0r = re[e], a0i = im[e], a1r = re[o], a1i = im[o];
        re[e] = c * a0r - s * a1r; im[e] = c * a0i - s * a1i;
        re[o] = s * a0r + c * a1r; im[o] = s * a0i + c * a1i;
    }
}
__device__ __forceinline__ void rx_lane(float re[8], float im[8], float c, float s, int m) {
#pragma unroll
    for (int j = 0; j < 8; j++) {
        float orr = __shfl_xor_sync(FULLM, re[j], m);
        float oii = __shfl_xor_sync(FULLM, im[j], m);
        re[j] = c * re[j] + s * oii;
        im[j] = c * im[j] - s * orr;
    }
}
__device__ __forceinline__ void ry_lane(float re[8], float im[8], float c, float s, int m, int bit) {
    float t = bit ? s : -s;
#pragma unroll
    for (int j = 0; j < 8; j++) {
        float orr = __shfl_xor_sync(FULLM, re[j], m);
        float oii = __shfl_xor_sync(FULLM, im[j], m);
        re[j] = c * re[j] + t * orr;
        im[j] = c * im[j] + t * oii;
    }
}

template<int T>
__device__ __forceinline__ void apply_one(float re[8], float im[8], int lane) {
    constexpr int kind = OpK<T>::kind;
    constexpr float c = OpK<T>::c;
    constexpr float s = OpK<T>::s;
    if constexpr (kind == 3) {
        constexpr int pc = OpK<T>::pa;
        constexpr int pt = OpK<T>::pb;
        if constexpr (pt >= 3) {
            constexpr int m = 1 << (pt - 3);
            if constexpr (pc >= 3) {
                int ctrl = (lane >> (pc - 3)) & 1;
#pragma unroll
                for (int j = 0; j < 8; j++) {
                    float orr = __shfl_xor_sync(FULLM, re[j], m);
                    float oii = __shfl_xor_sync(FULLM, im[j], m);
                    re[j] = ctrl ? orr : re[j];
                    im[j] = ctrl ? oii : im[j];
                }
            } else {
#pragma unroll
                for (int j = 0; j < 8; j++) {
                    if ((j >> pc) & 1) {
                        re[j] = __shfl_xor_sync(FULLM, re[j], m);
                        im[j] = __shfl_xor_sync(FULLM, im[j], m);
                    }
                }
            }
        } else {
            constexpr int tm = 1 << pt;
            if constexpr (pc >= 3) {
                if ((lane >> (pc - 3)) & 1) {
#pragma unroll
                    for (int e = 0; e < 8; e++) {
                        if (e & tm) continue;
                        int o = e | tm;
                        float tr = re[e]; re[e] = re[o]; re[o] = tr;
                        float ti = im[e]; im[e] = im[o]; im[o] = ti;
                    }
                }
            } else {
#pragma unroll
                for (int e = 0; e < 8; e++) {
                    if ((e & tm) || !((e >> pc) & 1)) continue;
                    int o = e | tm;
                    float tr = re[e]; re[e] = re[o]; re[o] = tr;
                    float ti = im[e]; im[e] = im[o]; im[o] = ti;
                }
            }
        }
    } else if constexpr (kind == 2) {
        constexpr int p = OpK<T>::pa;
        if constexpr (p >= 3) {
            int bit = (lane >> (p - 3)) & 1;
            float t = bit ? -s : s;
            float tn = -t;
#pragma unroll
            for (int j = 0; j < 8; j++) {
                float r = re[j], i = im[j];
                re[j] = fmaf(t, i, c * r);
                im[j] = fmaf(tn, r, c * i);
            }
        } else {
#pragma unroll
            for (int j = 0; j < 8; j++) {
                float sg = ((j >> p) & 1) ? -s : s;
                float r = re[j], i = im[j];
                re[j] = fmaf(sg, i, c * r);
                im[j] = fmaf(-sg, r, c * i);
            }
        }
    } else if constexpr (kind == 0) {
        constexpr int p = OpK<T>::pa;
        if constexpr (p >= 3)      rx_lane(re, im, c, s, 1 << (p - 3));
        else if constexpr (p == 0) rx_loc<0>(re, im, c, s);
        else if constexpr (p == 1) rx_loc<1>(re, im, c, s);
        else                       rx_loc<2>(re, im, c, s);
    } else {
        constexpr int p = OpK<T>::pa;
        if constexpr (p >= 3)      ry_lane(re, im, c, s, 1 << (p - 3), (lane >> (p - 3)) & 1);
        else if constexpr (p == 0) ry_loc<0>(re, im, c, s);
        else if constexpr (p == 1) ry_loc<1>(re, im, c, s);
        else                       ry_loc<2>(re, im, c, s);
    }
}
template<int T>
__device__ __forceinline__ void apply_seq(float re[8], float im[8], int lane) {
    if constexpr (T < 30) {
        apply_one<T>(re, im, lane);
        apply_seq<T + 1>(re, im, lane);
    }
}

template<int W>
__device__ __forceinline__ void init_lane_factor(float& fr, const float cs[8],
                                                 const float sn[8], int lane) {
    if constexpr (W < 8) {
        constexpr int p = PBit<W>::p;
        if constexpr (p >= 3) {
            int bit = (lane >> (p - 3)) & 1;
            fr *= bit ? sn[W] : cs[W];
        }
        init_lane_factor<W + 1>(fr, cs, sn, lane);
    }
}
template<int J, int W>
__device__ __forceinline__ void reg_factor_acc(float& g, const float cs[8], const float sn[8]) {
    if constexpr (W < 8) {
        constexpr int p = PBit<W>::p;
        if constexpr (p < 3) {
            if constexpr (((J >> p) & 1) != 0) g *= sn[W];
            else                               g *= cs[W];
        }
        reg_factor_acc<J, W + 1>(g, cs, sn);
    }
}
template<int J>
__device__ __forceinline__ void init_amps(float re[8], float im[8], float fr,
                                          const float cs[8], const float sn[8]) {
    if constexpr (J < 8) {
        float g = fr;
        reg_factor_acc<J, 0>(g, cs, sn);
        re[J] = g;
        im[J] = 0.f;
        init_amps<J + 1>(re, im, fr, cs, sn);
    }
}

// ======================================================================
// measure with fused final-RX (Heisenberg): RX(th)† Z RX(th) = cos·Z + sin·Y
// (proven round 13-14, rel_err 1.03e-7)
// ======================================================================
template<int W>
__device__ __forceinline__ void measure_zy(float zp[8], const float re[8], const float im[8],
                                           const float pj[8], float tot,
                                           const float* __restrict__ phiq, int lane) {
    if constexpr (W < 8) {
        constexpr int p = PBit<W>::p;
        float snw, cw;
        __sincosf(phiq[W], &snw, &cw);           // FULL angle
        if constexpr (p >= 3) {
            constexpr int m = 1 << (p - 3);
            float y = 0.f;
#pragma unroll
            for (int j = 0; j < 8; j++) {
                float pr = __shfl_xor_sync(FULLM, re[j], m);
                float pi = __shfl_xor_sync(FULLM, im[j], m);
                y = fmaf(re[j], pi, y);
                y = fmaf(-im[j], pr, y);
            }
            float v = fmaf(snw, y, cw * tot);
            zp[W] = ((lane >> (p - 3)) & 1) ? -v : v;
        } else {
            constexpr int tm = 1 << p;
            float z = 0.f, y = 0.f;
#pragma unroll
            for (int e = 0; e < 8; e++) {
                if (e & tm) continue;
                int o = e | tm;
                z += pj[e] - pj[o];
                y = fmaf(re[e], im[o], y);
                y = fmaf(-im[e], re[o], y);
            }
            zp[W] = fmaf(cw, z, (2.f * snw) * y);
        }
        measure_zy<W + 1>(zp, re, im, pj, tot, phiq, lane);
    }
}

__device__ __forceinline__ float tanhfast(float x) {
    float y;
    asm("tanh.approx.f32 %0, %1;" : "=f"(y) : "f"(x));
    return y;
}

// ======================================================================
// kernel 1: embed + LSTM fused (CH=16). 8 warps: wid7 = LSTM (hi-wid
// arbiter priority), wid0-6 = embed.  bphi folded into zbuf at embed;
// 0.5x folded into Wo/bo for sigmoid lanes; 4x2 z-dot chains.
// ======================================================================
__global__ void __launch_bounds__(256) k_prod(
    const float* __restrict__ emb, const float* __restrict__ Win,
    const float* __restrict__ b_in, const float* __restrict__ phi,
    const float* __restrict__ Wout, const float* __restrict__ b_out,
    const long long* __restrict__ sent)
{
    __shared__ float sW[32 * 76];
    __shared__ float zbuf[2][CH][32];
    __shared__ int   s_is64;

    int tid = threadIdx.x;
    int wid = tid >> 5;
    int lane = tid & 31;
    int b = blockIdx.x;

    for (int i = tid; i < 32 * 72; i += 256) {
        int r = i / 72, f = i - r * 72;
        sW[r * 76 + f] = Win[i];
    }
    if (tid == 0) {
        int cnt = 0;
        for (int i = 0; i < 8; i++) {
            long long v = sent[i];
            cnt += (v >= 0 && v < V_SZ);
        }
        s_is64 = (cnt >= 5);
    }
    // every warp loads bphi for its lane (embed adds it into zbuf)
    float bphi = b_in[lane] + phi[lane];
    __syncthreads();
    bool is64 = (s_is64 != 0);

    float Wh[8], Wo[8], bo = 0.f, hn = 0.f, cst = 0.f;
    int hh = 0, basem = 0; bool isg = false;
    if (wid == LSTM_WID) {
        basem = lane & 24; isg = (basem == 16);
        float sc = isg ? 1.f : 0.5f;     // fold sigmoid's x/2 into weights
#pragma unroll
        for (int j = 0; j < 8; j++) Wh[j] = sW[lane * 76 + 64 + j];
#pragma unroll
        for (int j = 0; j < 8; j++) Wo[j] = sc * Wout[lane * 8 + j];
        bo = sc * b_out[lane];
        hh = lane & 7;
    }

    for (int i = 0; i <= NCH; i++) {
        if (wid != LSTM_WID) {
            int ce = i;
            if (ce < NCH) {
                for (int t = wid; t < CH; t += NEMB) {
                    int s = ce * CH + t;
                    long long tok = is64 ? sent[s * B_SZ + b]
                                         : (long long)(((const int*)sent)[s * B_SZ + b]);
                    const float4* er = reinterpret_cast<const float4*>(emb + (size_t)tok * E_DIM);
                    const float4* wr = reinterpret_cast<const float4*>(&sW[lane * 76]);
                    float a0 = bphi, a1 = 0.f, a2 = 0.f, a3 = 0.f;
#pragma unroll
                    for (int k = 0; k < 16; k++) {
                        float4 e4 = er[k];
                        float4 w4 = wr[k];
                        a0 = fmaf(e4.x, w4.x, a0); a1 = fmaf(e4.y, w4.y, a1);
                        a2 = fmaf(e4.z, w4.z, a2); a3 = fmaf(e4.w, w4.w, a3);
                    }
                    zbuf[ce & 1][t][lane] = (a0 + a1) + (a2 + a3);
                }
            }
        } else {
            int cl = i - 1;
            if (cl >= 0) {
                float zt[CH];
#pragma unroll
                for (int t = 0; t < CH; t++) zt[t] = zbuf[cl & 1][t][lane];
#pragma unroll 1
                for (int t = 0; t < CH; t++) {
                    // z-dot: 4 chains of depth 2 + add tree (bphi already in zt)
                    float h0 = __shfl_sync(FULLM, hn, 0);
                    float h1 = __shfl_sync(FULLM, hn, 1);
                    float h2 = __shfl_sync(FULLM, hn, 2);
                    float h3 = __shfl_sync(FULLM, hn, 3);
                    float h4 = __shfl_sync(FULLM, hn, 4);
                    float h5 = __shfl_sync(FULLM, hn, 5);
                    float h6 = __shfl_sync(FULLM, hn, 6);
                    float h7 = __shfl_sync(FULLM, hn, 7);
                    float p0 = fmaf(Wh[1], h1, fmaf(Wh[0], h0, zt[t]));
                    float p1 = fmaf(Wh[3], h3, Wh[2] * h2);
                    float p2 = fmaf(Wh[5], h5, Wh[4] * h4);
                    float p3 = fmaf(Wh[7], h7, Wh[6] * h6);
                    float myc = __cosf((p0 + p1) + (p2 + p3));
                    float cj[8];
#pragma unroll
                    for (int j = 0; j < 8; j++) cj[j] = __shfl_sync(FULLM, myc, basem + j);
                    // split-Horner: arg = (bo + A-chain) + P4 * B-chain
                    float tA = Wo[3];
                    tA = fmaf(cj[3], tA, Wo[2]);
                    tA = fmaf(cj[2], tA, Wo[1]);
                    tA = fmaf(cj[1], tA, Wo[0]);
                    float Ab = fmaf(cj[0], tA, bo);
                    float tB = Wo[7];
                    tB = fmaf(cj[7], tB, Wo[6]);
                    tB = fmaf(cj[6], tB, Wo[5]);
                    tB = fmaf(cj[5], tB, Wo[4]);
                    float Bv = cj[4] * tB;
                    float P4 = (cj[0] * cj[1]) * (cj[2] * cj[3]);
                    float arg = fmaf(P4, Bv, Ab);
                    float ta = tanhfast(arg);
                    float a = isg ? ta : fmaf(0.5f, ta, 0.5f);
                    float vf = __shfl_sync(FULLM, a, hh);
                    float vi = __shfl_sync(FULLM, a, 8 + hh);
                    float vg = __shfl_sync(FULLM, a, 16 + hh);
                    float vo = __shfl_sync(FULLM, a, 24 + hh);
                    cst = fmaf(vf, cst, vi * vg);
                    hn = vo * tanhfast(cst);
                    if (lane < 8) g_h[(b * S_LEN + cl * CH + t) * H_DIM + lane] = hn;
                }
            }
        }
        __syncthreads();
    }
}

// ======================================================================
// kernel 2: QFC statevector head — Heisenberg-fused final RX
// ======================================================================
__global__ void __launch_bounds__(256, 6) k_qfc(const float* __restrict__ phiq,
                                                const float* __restrict__ Whead,
                                                const float* __restrict__ b_head,
                                                float* __restrict__ out) {
    int warp = (blockIdx.x * blockDim.x + threadIdx.x) >> 5;
    int lane = threadIdx.x & 31;

    float re[8], im[8];
    {
        float cs[8], sn[8];
#pragma unroll
        for (int w = 0; w < 8; w++) {
            __sincosf(0.5f * g_h[warp * 8 + w], &sn[w], &cs[w]);
        }
        float fr = 1.f;
        init_lane_factor<0>(fr, cs, sn, lane);
        init_amps<0>(re, im, fr, cs, sn);
    }

    apply_seq<0>(re, im, lane);

    float pj[8];
    float tot = 0.f;
#pragma unroll
    for (int j = 0; j < 8; j++) {
        pj[j] = re[j] * re[j] + im[j] * im[j];
        tot += pj[j];
    }
    float zp[8];
    measure_zy<0>(zp, re, im, pj, tot, phiq, lane);
#pragma unroll
    for (int off = 16; off >= 1; off >>= 1) {
#pragma unroll
        for (int w = 0; w < 8; w++) zp[w] += __shfl_xor_sync(FULLM, zp[w], off);
    }

    float logit = __int_as_float(0xff800000);
    if (lane < T_OUT) {
        float a = b_head[lane];
#pragma unroll
        for (int h = 0; h < 8; h++) a += zp[h] * Whead[lane * 8 + h];
        logit = a;
    }
    // softmax reduces: only lanes 0-11 carry data; lanes 12-15 are -inf/0,
    // so a 16-lane butterfly (offsets 8,4,2,1) suffices. Lanes 16+ compute
    // garbage that is never stored (their halves never mix with 0-15).
    float m = logit;
#pragma unroll
    for (int off = 8; off >= 1; off >>= 1) m = fmaxf(m, __shfl_xor_sync(FULLM, m, off));
    float e = (lane < T_OUT) ? __expf(logit - m) : 0.f;
#pragma unroll
    for (int off = 8; off >= 1; off >>= 1) e += __shfl_xor_sync(FULLM, e, off);
    if (lane < T_OUT) out[warp * T_OUT + lane] = logit - m - __logf(e);
}

// ======================================================================
extern "C" void kernel_launch(void* const* d_in, const int* in_sizes, int n_in,
                              void* d_out, int out_size) {
    const float* emb     = (const float*)d_in[0];
    const float* Win     = (const float*)d_in[1];
    const float* b_in    = (const float*)d_in[2];
    const float* phi     = (const float*)d_in[3];
    const float* Wout    = (const float*)d_in[4];
    const float* b_out   = (const float*)d_in[5];
    const float* phiq    = (const float*)d_in[6];
    const float* Whead   = (const float*)d_in[7];
    const float* b_head  = (const float*)d_in[8];
    const long long* sent = (const long long*)d_in[9];
    float* out = (float*)d_out;

    k_prod<<<B_SZ, 256>>>(emb, Win, b_in, phi, Wout, b_out, sent);
    k_qfc<<<NSAMP / 8, 256>>>(phiq, Whead, b_head, out);
}